// round 1
// baseline (speedup 1.0000x reference)
#include <cuda_runtime.h>
#include <math.h>

#define SQ   4096
#define DM   128
#define NH   4
#define DHD  32
#define NL   3
#define FFD  1024

// ---------------- scratch (device globals; no allocation) ----------------
__device__ float g_x[SQ * DM];        // running activation x
__device__ float g_qkv[SQ * 3 * DM];  // qkv projection
__device__ float g_ao[SQ * DM];       // attention out / fc1 out / misc
__device__ float g_tmp[SQ * FFD];     // FF intermediate / o-proj out / fc2 out
__device__ float g_xn[SQ * DM];       // normalized rows

// ---------------- simple copy ----------------
__global__ void copy_kernel(const float* __restrict__ src, float* __restrict__ dst, int n4) {
    int i = blockIdx.x * blockDim.x + threadIdx.x;
    if (i < n4) ((float4*)dst)[i] = ((const float4*)src)[i];
}

// ---------------- tiled GEMM: C[M,N] = A[M,K] @ W[N,K]^T + bias, epilogue ----------------
// EPI: 0 = none, 1 = relu, 2 = max(v, 1e-6)
template <int EPI>
__global__ __launch_bounds__(256)
void gemm_kernel(const float* __restrict__ A, const float* __restrict__ W,
                 const float* __restrict__ bias, float* __restrict__ C,
                 int M, int N, int K) {
    __shared__ float As[16][68];
    __shared__ float Bs[16][68];

    const int tid = threadIdx.x;
    const int tx = tid & 15;          // 0..15  (N direction)
    const int ty = tid >> 4;          // 0..15  (M direction)
    const int bm = blockIdx.y * 64;
    const int bn = blockIdx.x * 64;

    const int lr = tid >> 2;          // 0..63 load row
    const int lc = tid & 3;           // 0..3  load float4 col

    float acc[4][4];
#pragma unroll
    for (int i = 0; i < 4; i++)
#pragma unroll
        for (int j = 0; j < 4; j++) acc[i][j] = 0.f;

    for (int k0 = 0; k0 < K; k0 += 16) {
        float4 va = *(const float4*)(A + (size_t)(bm + lr) * K + k0 + lc * 4);
        float4 vb = *(const float4*)(W + (size_t)(bn + lr) * K + k0 + lc * 4);
        As[lc * 4 + 0][lr] = va.x; As[lc * 4 + 1][lr] = va.y;
        As[lc * 4 + 2][lr] = va.z; As[lc * 4 + 3][lr] = va.w;
        Bs[lc * 4 + 0][lr] = vb.x; Bs[lc * 4 + 1][lr] = vb.y;
        Bs[lc * 4 + 2][lr] = vb.z; Bs[lc * 4 + 3][lr] = vb.w;
        __syncthreads();

#pragma unroll
        for (int kk = 0; kk < 16; kk++) {
            float a[4], b[4];
#pragma unroll
            for (int i = 0; i < 4; i++) a[i] = As[kk][ty * 4 + i];
#pragma unroll
            for (int j = 0; j < 4; j++) b[j] = Bs[kk][tx * 4 + j];
#pragma unroll
            for (int i = 0; i < 4; i++)
#pragma unroll
                for (int j = 0; j < 4; j++)
                    acc[i][j] = fmaf(a[i], b[j], acc[i][j]);
        }
        __syncthreads();
    }

#pragma unroll
    for (int i = 0; i < 4; i++) {
        int row = bm + ty * 4 + i;
#pragma unroll
        for (int j = 0; j < 4; j++) {
            int col = bn + tx * 4 + j;
            float v = acc[i][j];
            if (bias) v += bias[col];
            if (EPI == 1) v = fmaxf(v, 0.f);
            if (EPI == 2) v = fmaxf(v, 1e-6f);
            C[(size_t)row * N + col] = v;
        }
    }
}

// ---------------- flash attention ----------------
// one thread per query; grid (SQ/128, NH); 128 threads
__global__ __launch_bounds__(128)
void attn_kernel(const float* __restrict__ qkv, float* __restrict__ out) {
    const int KT = 64;
    const int tid = threadIdx.x;
    const int h = blockIdx.y;
    const int s = blockIdx.x * 128 + tid;

    __shared__ float4 Ks[KT][8];
    __shared__ float4 Vs[KT][8];

    const float scale = 0.17677669529663687f;  // 1/sqrt(32)

    float4 q[8];
    const float4* qp = (const float4*)(qkv + (size_t)s * 384 + h * 32);
#pragma unroll
    for (int c = 0; c < 8; c++) {
        q[c] = qp[c];
        q[c].x *= scale; q[c].y *= scale; q[c].z *= scale; q[c].w *= scale;
    }

    float m = -1e30f, lsum = 0.f;
    float acc[32];
#pragma unroll
    for (int d = 0; d < 32; d++) acc[d] = 0.f;

    for (int kt = 0; kt < SQ; kt += KT) {
        __syncthreads();
#pragma unroll
        for (int i = 0; i < 4; i++) {
            int idx = tid + i * 128;     // 0..511
            int r = idx >> 3, c = idx & 7;
            Ks[r][c] = *(const float4*)(qkv + (size_t)(kt + r) * 384 + 128 + h * 32 + c * 4);
            Vs[r][c] = *(const float4*)(qkv + (size_t)(kt + r) * 384 + 256 + h * 32 + c * 4);
        }
        __syncthreads();

#pragma unroll 2
        for (int j = 0; j < KT; j++) {
            float sc = 0.f;
#pragma unroll
            for (int c = 0; c < 8; c++) {
                float4 k4 = Ks[j][c];
                sc = fmaf(q[c].x, k4.x, sc);
                sc = fmaf(q[c].y, k4.y, sc);
                sc = fmaf(q[c].z, k4.z, sc);
                sc = fmaf(q[c].w, k4.w, sc);
            }
            if (sc > m) {
                float corr = __expf(m - sc);
                m = sc;
                lsum *= corr;
#pragma unroll
                for (int d = 0; d < 32; d++) acc[d] *= corr;
            }
            float p = __expf(sc - m);
            lsum += p;
#pragma unroll
            for (int c = 0; c < 8; c++) {
                float4 v4 = Vs[j][c];
                acc[c * 4 + 0] = fmaf(p, v4.x, acc[c * 4 + 0]);
                acc[c * 4 + 1] = fmaf(p, v4.y, acc[c * 4 + 1]);
                acc[c * 4 + 2] = fmaf(p, v4.z, acc[c * 4 + 2]);
                acc[c * 4 + 3] = fmaf(p, v4.w, acc[c * 4 + 3]);
            }
        }
    }

    float inv = 1.f / lsum;
    float4* op = (float4*)(out + (size_t)s * DM + h * 32);
#pragma unroll
    for (int c = 0; c < 8; c++) {
        float4 o4;
        o4.x = acc[c * 4 + 0] * inv;
        o4.y = acc[c * 4 + 1] * inv;
        o4.z = acc[c * 4 + 2] * inv;
        o4.w = acc[c * 4 + 3] * inv;
        op[c] = o4;
    }
}

// ---------------- residual + layernorm: x = LN(x + o) * g + b ----------------
__global__ __launch_bounds__(128)
void add_ln_kernel(float* __restrict__ x, const float* __restrict__ o,
                   const float* __restrict__ g, const float* __restrict__ b) {
    const int r = blockIdx.x, t = threadIdx.x;
    const int lane = t & 31, warp = t >> 5;
    __shared__ float red1[4], red2[4];

    float v = x[(size_t)r * DM + t] + o[(size_t)r * DM + t];

    float ws = v;
#pragma unroll
    for (int off = 16; off > 0; off >>= 1) ws += __shfl_xor_sync(0xffffffffu, ws, off);
    if (lane == 0) red1[warp] = ws;
    __syncthreads();
    float mean = (red1[0] + red1[1] + red1[2] + red1[3]) * (1.f / DM);

    float dv = v - mean;
    float ws2 = dv * dv;
#pragma unroll
    for (int off = 16; off > 0; off >>= 1) ws2 += __shfl_xor_sync(0xffffffffu, ws2, off);
    if (lane == 0) red2[warp] = ws2;
    __syncthreads();
    float var = (red2[0] + red2[1] + red2[2] + red2[3]) * (1.f / DM);

    x[(size_t)r * DM + t] = dv * rsqrtf(var + 1e-5f) * g[t] + b[t];
}

// ---------------- row L2 normalize ----------------
__global__ __launch_bounds__(128)
void rownorm_kernel(const float* __restrict__ in, float* __restrict__ out) {
    const int r = blockIdx.x, t = threadIdx.x;
    const int lane = t & 31, warp = t >> 5;
    __shared__ float red[4];

    float v = in[(size_t)r * DM + t];
    float ws = v * v;
#pragma unroll
    for (int off = 16; off > 0; off >>= 1) ws += __shfl_xor_sync(0xffffffffu, ws, off);
    if (lane == 0) red[warp] = ws;
    __syncthreads();
    float nrm = red[0] + red[1] + red[2] + red[3];
    out[(size_t)r * DM + t] = v * rsqrtf(nrm);
}

// ---------------- launch ----------------
extern "C" void kernel_launch(void* const* d_in, const int* in_sizes, int n_in,
                              void* d_out, int out_size) {
    const float* src   = (const float*)d_in[0];
    const float* Wqkv  = (const float*)d_in[1];
    const float* bqkv  = (const float*)d_in[2];
    const float* Wo    = (const float*)d_in[3];
    const float* bo    = (const float*)d_in[4];
    const float* ln1g  = (const float*)d_in[5];
    const float* ln1b  = (const float*)d_in[6];
    const float* W1    = (const float*)d_in[7];
    const float* b1    = (const float*)d_in[8];
    const float* W2    = (const float*)d_in[9];
    const float* b2    = (const float*)d_in[10];
    const float* ln2g  = (const float*)d_in[11];
    const float* ln2b  = (const float*)d_in[12];
    const float* fc1W  = (const float*)d_in[13];
    const float* fc1b  = (const float*)d_in[14];
    const float* fc2W  = (const float*)d_in[15];
    const float* fc2b  = (const float*)d_in[16];
    float* out = (float*)d_out;

    float *x, *qkv, *ao, *tmp, *xn;
    cudaGetSymbolAddress((void**)&x,   g_x);
    cudaGetSymbolAddress((void**)&qkv, g_qkv);
    cudaGetSymbolAddress((void**)&ao,  g_ao);
    cudaGetSymbolAddress((void**)&tmp, g_tmp);
    cudaGetSymbolAddress((void**)&xn,  g_xn);

    // x = src
    copy_kernel<<<(SQ * DM / 4 + 255) / 256, 256>>>(src, x, SQ * DM / 4);

    for (int l = 0; l < NL; l++) {
        // qkv = x @ Wqkv[l]^T + bqkv[l]     [SQ, 384]
        gemm_kernel<0><<<dim3(384 / 64, SQ / 64), 256>>>(
            x, Wqkv + (size_t)l * 3 * DM * DM, bqkv + (size_t)l * 3 * DM,
            qkv, SQ, 3 * DM, DM);

        // attention -> ao [SQ, DM]
        attn_kernel<<<dim3(SQ / 128, NH), 128>>>(qkv, ao);

        // o = ao @ Wo[l]^T + bo[l] -> tmp [SQ, DM]
        gemm_kernel<0><<<dim3(DM / 64, SQ / 64), 256>>>(
            ao, Wo + (size_t)l * DM * DM, bo + (size_t)l * DM, tmp, SQ, DM, DM);

        // x = LN(x + o)
        add_ln_kernel<<<SQ, 128>>>(x, tmp, ln1g + l * DM, ln1b + l * DM);

        // f1 = relu(x @ W1^T + b1) -> tmp [SQ, FFD]
        gemm_kernel<1><<<dim3(FFD / 64, SQ / 64), 256>>>(
            x, W1 + (size_t)l * FFD * DM, b1 + (size_t)l * FFD, tmp, SQ, FFD, DM);

        // f2 = f1 @ W2^T + b2 -> ao [SQ, DM]
        gemm_kernel<0><<<dim3(DM / 64, SQ / 64), 256>>>(
            tmp, W2 + (size_t)l * DM * FFD, b2 + (size_t)l * DM, ao, SQ, DM, FFD);

        // x = LN(x + f2)
        add_ln_kernel<<<SQ, 128>>>(x, ao, ln2g + l * DM, ln2b + l * DM);
    }

    // fc1: relu -> ao
    gemm_kernel<1><<<dim3(DM / 64, SQ / 64), 256>>>(x, fc1W, fc1b, ao, SQ, DM, DM);
    // fc2 -> tmp
    gemm_kernel<0><<<dim3(DM / 64, SQ / 64), 256>>>(ao, fc2W, fc2b, tmp, SQ, DM, DM);
    // row normalize -> xn
    rownorm_kernel<<<SQ, 128>>>(tmp, xn);
    // out = max(xn @ xn^T, 1e-6)
    gemm_kernel<2><<<dim3(SQ / 64, SQ / 64), 256>>>(xn, xn, (const float*)nullptr,
                                                    out, SQ, SQ, DM);
}